// round 10
// baseline (speedup 1.0000x reference)
#include <cuda_runtime.h>
#include <cuda_fp16.h>
#include <cstdint>

// ---------------- problem dims ----------------
#define B_   32
#define T_   4096
#define DIN_ 256
#define H_   256
#define BT_  (B_ * T_)

// ---------------- fused tiling ------------------
#define TCH   128             // tokens per chunk
#define NCHK  (T_ / TCH)      // 32 chunks
#define KC    64              // K halves per k-stage (128B rows)
#define NKC   (DIN_ / KC)     // 4 k-stages per chunk
#define NSTG  (NCHK * NKC)    // 128 total k-stages
#define HSL   32              // h channels per CTA slice

// smem layout (bytes)
#define SM_A     0                  // 3 stages x 16384 (A: 128 tok x 64 halves)
#define SM_W     49152              // 4 panels x 8192 (W: 32 z-rows + 32 h-rows x 64 halves)
#define SM_CV    81920              // 128 tok x 32 h x half2 = 16384
#define SM_SEGP  98304              // 16 x 32 floats = 2048
#define SM_SEGS  100352             // 16 x 32 floats = 2048
#define SM_HC    102400             // 32 floats carry
#define SMEM_FUSED 102528

// cv smem swizzle: word index for (token t, channel h), h in [0,32)
#define CVIDX(t, h) ((t) * 32 + ((h) ^ (((t) & 7) << 2)))

// ---------------- scratch ----------------------
__device__ __half g_Xh[(size_t)BT_ * DIN_];
__device__ __half g_Wzh[H_ * DIN_];
__device__ __half g_Whh[H_ * DIN_];

// ---------------- fp32 -> fp16 convert ----------------
__global__ void __launch_bounds__(256) convert_kernel(
    const float* __restrict__ X, const float* __restrict__ Wz, const float* __restrict__ Wh)
{
    const size_t i = (size_t)blockIdx.x * blockDim.x + threadIdx.x;
    const size_t stride = (size_t)gridDim.x * blockDim.x;
    const size_t XF4 = (size_t)BT_ * DIN_ / 4;
    const size_t WF4 = H_ * DIN_ / 4;

    const float4* X4 = reinterpret_cast<const float4*>(X);
    uint2* OX = reinterpret_cast<uint2*>(g_Xh);
    for (size_t j = i; j < XF4; j += stride) {
        float4 v = X4[j];
        __half2 h0 = __floats2half2_rn(v.x, v.y);
        __half2 h1 = __floats2half2_rn(v.z, v.w);
        OX[j] = make_uint2(*reinterpret_cast<uint32_t*>(&h0), *reinterpret_cast<uint32_t*>(&h1));
    }
    const float4* Wz4 = reinterpret_cast<const float4*>(Wz);
    const float4* Wh4 = reinterpret_cast<const float4*>(Wh);
    uint2* OZ = reinterpret_cast<uint2*>(g_Wzh);
    uint2* OH = reinterpret_cast<uint2*>(g_Whh);
    for (size_t j = i; j < WF4; j += stride) {
        float4 v = Wz4[j];
        __half2 h0 = __floats2half2_rn(v.x, v.y);
        __half2 h1 = __floats2half2_rn(v.z, v.w);
        OZ[j] = make_uint2(*reinterpret_cast<uint32_t*>(&h0), *reinterpret_cast<uint32_t*>(&h1));
        v = Wh4[j];
        h0 = __floats2half2_rn(v.x, v.y);
        h1 = __floats2half2_rn(v.z, v.w);
        OH[j] = make_uint2(*reinterpret_cast<uint32_t*>(&h0), *reinterpret_cast<uint32_t*>(&h1));
    }
}

// ---------------- helpers ------------------
__device__ __forceinline__ uint32_t smem_u32(const void* p) {
    uint32_t r;
    asm("{\n\t.reg .u64 t;\n\tcvta.to.shared.u64 t, %1;\n\tcvt.u32.u64 %0, t;\n\t}"
        : "=r"(r) : "l"(p));
    return r;
}
__device__ __forceinline__ void cp16(uint32_t dst, const void* src) {
    asm volatile("cp.async.cg.shared.global [%0], [%1], 16;" :: "r"(dst), "l"(src));
}
#define CP_COMMIT()  asm volatile("cp.async.commit_group;" ::: "memory")
#define CP_WAIT1()   asm volatile("cp.async.wait_group 1;" ::: "memory")
#define SWZ(o) ((o) ^ ((((uint32_t)(o)) >> 3) & 0x70))

__device__ __forceinline__ void ldm_x4(uint32_t& r0, uint32_t& r1, uint32_t& r2, uint32_t& r3,
                                       uint32_t addr) {
    asm volatile("ldmatrix.sync.aligned.m8n8.x4.shared.b16 {%0,%1,%2,%3}, [%4];"
                 : "=r"(r0), "=r"(r1), "=r"(r2), "=r"(r3) : "r"(addr));
}
__device__ __forceinline__ void mma_f16(float* d, const uint32_t* a, uint32_t b0, uint32_t b1) {
    asm volatile("mma.sync.aligned.m16n8k16.row.col.f32.f16.f16.f32 "
                 "{%0,%1,%2,%3}, {%4,%5,%6,%7}, {%8,%9}, {%0,%1,%2,%3};"
                 : "+f"(d[0]), "+f"(d[1]), "+f"(d[2]), "+f"(d[3])
                 : "r"(a[0]), "r"(a[1]), "r"(a[2]), "r"(a[3]), "r"(b0), "r"(b1));
}

__device__ __forceinline__ float sigmoid_f(float x) {
    return __fdividef(1.f, 1.f + __expf(-x));
}
__device__ __forceinline__ float g_act(float x) {
    return x >= 0.f ? x + 0.5f : sigmoid_f(x);
}
__device__ __forceinline__ uint32_t pack_cv(float c, float v) {
    __half2 p = __floats2half2_rn(c, v);
    return *reinterpret_cast<uint32_t*>(&p);
}

// ---------------- fused GEMM + activation + scan ----------------
// grid: (slice [0,8), batch [0,32)); block 512 = 16 warps laid out 8(M) x 2(N)
__global__ void __launch_bounds__(512, 2) fused_kernel(
    const float* __restrict__ bz, const float* __restrict__ bh,
    const float* __restrict__ h0g, float* __restrict__ out)
{
    extern __shared__ char smem[];
    const uint32_t sbase = smem_u32(smem);

    float*   segP = reinterpret_cast<float*>(smem + SM_SEGP);
    float*   segS = reinterpret_cast<float*>(smem + SM_SEGS);
    float*   hcF  = reinterpret_cast<float*>(smem + SM_HC);
    __half2* scvH = reinterpret_cast<__half2*>(smem + SM_CV);
    uint32_t* scvU = reinterpret_cast<uint32_t*>(smem + SM_CV);

    const int tid  = threadIdx.x;
    const int lane = tid & 31;
    const int wid  = tid >> 5;
    const int wm   = wid >> 1;    // 0..7 (token dir, 16 rows each)
    const int wn   = wid & 1;     // 0..1 (h dir, 16 cols each)
    const int grp  = lane >> 2;   // 0..7
    const int tg   = lane & 3;    // 0..3
    const int lrow = ((lane >> 3) & 1) * 8 + (lane & 7);
    const int lkh  = (lane >> 4) * 16;

    const int slice = blockIdx.x;
    const int b     = blockIdx.y;
    const int hbase = slice * HSL;

    // scan-phase mapping: warp = segment (8 tokens), lane = h channel
    const int seg = tid >> 5;      // 0..15
    const int hch = tid & 31;      // h channel within slice

    // init h carry
    if (tid < HSL) hcF[tid] = g_act(h0g[b * H_ + hbase + tid]);

    // bias preload (per-thread h columns)
    float bzr[2][2], bhr[2][2];
    #pragma unroll
    for (int nt = 0; nt < 2; nt++) {
        int col = hbase + wn * 16 + nt * 8 + 2 * tg;
        bzr[nt][0] = bz[col];     bzr[nt][1] = bz[col + 1];
        bhr[nt][0] = bh[col];     bhr[nt][1] = bh[col + 1];
    }

    const uint4* Xh4  = reinterpret_cast<const uint4*>(g_Xh);
    const uint4* Wzh4 = reinterpret_cast<const uint4*>(g_Wzh);
    const uint4* Whh4 = reinterpret_cast<const uint4*>(g_Whh);

    auto ld_A = [&](int s) {
        const uint32_t sb = sbase + SM_A + (s % 3) * 16384;
        const size_t tok0 = (size_t)b * T_ + (size_t)(s >> 2) * TCH;
        const int kc = s & 3;
        #pragma unroll
        for (int i = 0; i < 2; i++) {
            int q = tid + i * 512;
            int r = q >> 3, u = q & 7;
            cp16(sb + SWZ(r * 128 + u * 16), Xh4 + (tok0 + r) * 32 + kc * 8 + u);
        }
    };
    auto ld_W = [&]() {
        #pragma unroll
        for (int i = 0; i < 4; i++) {
            int q = tid + i * 512;            // 0..2047
            int c = q >> 9, rem = q & 511;    // panel, chunk in panel
            int r = rem >> 3, u = rem & 7;    // row 0..63, 16B unit
            const uint4* src = (r < 32) ? (Wzh4 + (size_t)(hbase + r) * 32 + c * 8 + u)
                                        : (Whh4 + (size_t)(hbase + r - 32) * 32 + c * 8 + u);
            cp16(sbase + SM_W + c * 8192 + SWZ(r * 128 + u * 16), src);
        }
    };

    float accZ[2][4], accH[2][4];
    #pragma unroll
    for (int nt = 0; nt < 2; nt++)
        #pragma unroll
        for (int q = 0; q < 4; q++) { accZ[nt][q] = 0.f; accH[nt][q] = 0.f; }

    ld_W(); ld_A(0); CP_COMMIT();
    ld_A(1); CP_COMMIT();

    #pragma unroll 1
    for (int s = 0; s < NSTG; s++) {
        CP_WAIT1();
        __syncthreads();

        if (s + 2 < NSTG) { ld_A(s + 2); CP_COMMIT(); }
        else              { CP_COMMIT(); }   // dummy: uniform group count

        const uint32_t aBase = sbase + SM_A + (s % 3) * 16384;
        const uint32_t wBase = sbase + SM_W + (s & 3) * 8192;

        #pragma unroll
        for (int ks = 0; ks < KC / 16; ks++) {
            const int kb = ks * 32 + lkh;
            uint32_t a[4], z[4], hh[4];
            ldm_x4(a[0], a[1], a[2], a[3],
                   aBase + SWZ((wm * 16 + lrow) * 128 + kb));
            ldm_x4(z[0], z[1], z[2], z[3],
                   wBase + SWZ((wn * 16 + lrow) * 128 + kb));
            ldm_x4(hh[0], hh[1], hh[2], hh[3],
                   wBase + SWZ((32 + wn * 16 + lrow) * 128 + kb));
            #pragma unroll
            for (int nt = 0; nt < 2; nt++) {
                mma_f16(accZ[nt], a, z[nt], z[nt + 2]);
                mma_f16(accH[nt], a, hh[nt], hh[nt + 2]);
            }
        }

        if ((s & 3) == 3) {
            const int chunk = s >> 2;

            // ---- activation -> cv smem ----
            #pragma unroll
            for (int nt = 0; nt < 2; nt++) {
                const int col = wn * 16 + nt * 8 + 2 * tg;   // local h
                const int r0  = wm * 16 + grp;               // local token
                float k0  = accZ[nt][0] + bzr[nt][0];
                float k1  = accZ[nt][1] + bzr[nt][1];
                float k2  = accZ[nt][2] + bzr[nt][0];
                float k3  = accZ[nt][3] + bzr[nt][1];
                float kh0 = accH[nt][0] + bhr[nt][0];
                float kh1 = accH[nt][1] + bhr[nt][1];
                float kh2 = accH[nt][2] + bhr[nt][0];
                float kh3 = accH[nt][3] + bhr[nt][1];
                float z0 = sigmoid_f(k0), z1 = sigmoid_f(k1);
                float z2 = sigmoid_f(k2), z3 = sigmoid_f(k3);
                uint2 p0 = make_uint2(pack_cv(1.f - z0, z0 * g_act(kh0)),
                                      pack_cv(1.f - z1, z1 * g_act(kh1)));
                uint2 p1 = make_uint2(pack_cv(1.f - z2, z2 * g_act(kh2)),
                                      pack_cv(1.f - z3, z3 * g_act(kh3)));
                *reinterpret_cast<uint2*>(&scvU[CVIDX(r0,     col)]) = p0;
                *reinterpret_cast<uint2*>(&scvU[CVIDX(r0 + 8, col)]) = p1;
            }
            __syncthreads();

            // ---- segment aggregate (8 tokens per thread) ----
            float P = 1.f, S = 0.f;
            const int tokb = seg * 8;
            #pragma unroll
            for (int j = 0; j < 8; j++) {
                float2 cv = __half22float2(scvH[CVIDX(tokb + j, hch)]);
                S = fmaf(cv.x, S, cv.y);
                P *= cv.x;
            }
            segP[seg * 32 + hch] = P;
            segS[seg * 32 + hch] = S;
            __syncthreads();

            // ---- combine: prefix over segments + carry ----
            float hin = hcF[hch];
            #pragma unroll
            for (int q = 0; q < 15; q++)
                if (q < seg) hin = fmaf(segP[q * 32 + hch], hin, segS[q * 32 + hch]);
            __syncthreads();   // all carry reads done before seg15 overwrites

            // ---- replay + emit ----
            float hv = hin;
            size_t obase = ((size_t)b * T_ + (size_t)chunk * TCH + tokb) * H_ + hbase + hch;
            #pragma unroll
            for (int j = 0; j < 8; j++) {
                float2 cv = __half22float2(scvH[CVIDX(tokb + j, hch)]);
                hv = fmaf(cv.x, hv, cv.y);
                out[obase + (size_t)j * H_] = hv;
            }
            if (seg == 15) hcF[hch] = hv;
            __syncthreads();

            // reset accumulators
            #pragma unroll
            for (int nt = 0; nt < 2; nt++)
                #pragma unroll
                for (int q = 0; q < 4; q++) { accZ[nt][q] = 0.f; accH[nt][q] = 0.f; }
        }
    }
}

// ---------------- launch -------------------------------------------------
extern "C" void kernel_launch(void* const* d_in, const int* in_sizes, int n_in,
                              void* d_out, int out_size)
{
    const float* x  = (const float*)d_in[0];
    const float* h0 = (const float*)d_in[1];
    const float* Wz = (const float*)d_in[2];
    const float* bz = (const float*)d_in[3];
    const float* Wh = (const float*)d_in[4];
    const float* bh = (const float*)d_in[5];
    float* out = (float*)d_out;

    convert_kernel<<<512, 256>>>(x, Wz, Wh);

    cudaFuncSetAttribute(fused_kernel, cudaFuncAttributeMaxDynamicSharedMemorySize, SMEM_FUSED);
    dim3 fgrid(H_ / HSL, B_);            // (8, 32) = 256 CTAs
    fused_kernel<<<fgrid, 512, SMEM_FUSED>>>(bz, bh, h0, out);
}

// round 11
// speedup vs baseline: 1.1615x; 1.1615x over previous
#include <cuda_runtime.h>
#include <cuda_fp16.h>
#include <cstdint>

// ---------------- problem dims ----------------
#define B_   32
#define T_   4096
#define DIN_ 256
#define H_   256
#define BT_  (B_ * T_)

// ---------------- fused tiling ------------------
#define TCH   128             // tokens per chunk
#define NCHK  (T_ / TCH)      // 32 chunks
#define KC    64              // K halves per k-stage (128B rows)
#define NKC   (DIN_ / KC)     // 4 k-stages per chunk
#define NSTG  (NCHK * NKC)    // 128 total k-stages
#define HSL   64              // h channels per CTA slice

// smem layout (bytes)
#define SM_A     0                  // 4 stages x 16384 (A: 128 tok x 64 halves)
#define SM_W     65536              // 4 panels x 16384 (W: 64 z-rows + 64 h-rows x 64 halves)
#define SM_CV    131072             // 128 tok x 64 h x half2 = 32768
#define SM_SEGP  163840             // 8 x 64 floats
#define SM_SEGS  165888             // 8 x 64 floats
#define SM_HC    167936             // 64 floats carry
#define SMEM_FUSED 168192

// cv smem swizzle: word index for (token t, channel h)
#define CVIDX(t, h) ((t) * 64 + ((h) ^ (((t) & 7) << 3)))

// ---------------- scratch ----------------------
__device__ __half g_Xh[(size_t)BT_ * DIN_];
__device__ __half g_Wzh[H_ * DIN_];
__device__ __half g_Whh[H_ * DIN_];

// ---------------- fp32 -> fp16 convert ----------------
__global__ void __launch_bounds__(256) convert_kernel(
    const float* __restrict__ X, const float* __restrict__ Wz, const float* __restrict__ Wh)
{
    const size_t i = (size_t)blockIdx.x * blockDim.x + threadIdx.x;
    const size_t stride = (size_t)gridDim.x * blockDim.x;
    const size_t XF4 = (size_t)BT_ * DIN_ / 4;
    const size_t WF4 = H_ * DIN_ / 4;

    const float4* X4 = reinterpret_cast<const float4*>(X);
    uint2* OX = reinterpret_cast<uint2*>(g_Xh);
    for (size_t j = i; j < XF4; j += stride) {
        float4 v = X4[j];
        __half2 h0 = __floats2half2_rn(v.x, v.y);
        __half2 h1 = __floats2half2_rn(v.z, v.w);
        OX[j] = make_uint2(*reinterpret_cast<uint32_t*>(&h0), *reinterpret_cast<uint32_t*>(&h1));
    }
    const float4* Wz4 = reinterpret_cast<const float4*>(Wz);
    const float4* Wh4 = reinterpret_cast<const float4*>(Wh);
    uint2* OZ = reinterpret_cast<uint2*>(g_Wzh);
    uint2* OH = reinterpret_cast<uint2*>(g_Whh);
    for (size_t j = i; j < WF4; j += stride) {
        float4 v = Wz4[j];
        __half2 h0 = __floats2half2_rn(v.x, v.y);
        __half2 h1 = __floats2half2_rn(v.z, v.w);
        OZ[j] = make_uint2(*reinterpret_cast<uint32_t*>(&h0), *reinterpret_cast<uint32_t*>(&h1));
        v = Wh4[j];
        h0 = __floats2half2_rn(v.x, v.y);
        h1 = __floats2half2_rn(v.z, v.w);
        OH[j] = make_uint2(*reinterpret_cast<uint32_t*>(&h0), *reinterpret_cast<uint32_t*>(&h1));
    }
}

// ---------------- helpers ------------------
__device__ __forceinline__ uint32_t smem_u32(const void* p) {
    uint32_t r;
    asm("{\n\t.reg .u64 t;\n\tcvta.to.shared.u64 t, %1;\n\tcvt.u32.u64 %0, t;\n\t}"
        : "=r"(r) : "l"(p));
    return r;
}
__device__ __forceinline__ void cp16(uint32_t dst, const void* src) {
    asm volatile("cp.async.cg.shared.global [%0], [%1], 16;" :: "r"(dst), "l"(src));
}
#define CP_COMMIT()  asm volatile("cp.async.commit_group;" ::: "memory")
#define CP_WAIT2()   asm volatile("cp.async.wait_group 2;" ::: "memory")
#define SWZ(o) ((o) ^ ((((uint32_t)(o)) >> 3) & 0x70))

__device__ __forceinline__ void ldm_x4(uint32_t& r0, uint32_t& r1, uint32_t& r2, uint32_t& r3,
                                       uint32_t addr) {
    asm volatile("ldmatrix.sync.aligned.m8n8.x4.shared.b16 {%0,%1,%2,%3}, [%4];"
                 : "=r"(r0), "=r"(r1), "=r"(r2), "=r"(r3) : "r"(addr));
}
__device__ __forceinline__ void mma_f16(float* d, const uint32_t* a, uint32_t b0, uint32_t b1) {
    asm volatile("mma.sync.aligned.m16n8k16.row.col.f32.f16.f16.f32 "
                 "{%0,%1,%2,%3}, {%4,%5,%6,%7}, {%8,%9}, {%0,%1,%2,%3};"
                 : "+f"(d[0]), "+f"(d[1]), "+f"(d[2]), "+f"(d[3])
                 : "r"(a[0]), "r"(a[1]), "r"(a[2]), "r"(a[3]), "r"(b0), "r"(b1));
}

__device__ __forceinline__ float sigmoid_f(float x) {
    return __fdividef(1.f, 1.f + __expf(-x));
}
__device__ __forceinline__ float g_act(float x) {
    return x >= 0.f ? x + 0.5f : sigmoid_f(x);
}
__device__ __forceinline__ uint32_t pack_cv(float c, float v) {
    __half2 p = __floats2half2_rn(c, v);
    return *reinterpret_cast<uint32_t*>(&p);
}

// ---------------- fused GEMM + activation + scan ----------------
// grid: (slice [0,4), batch [0,32)); block 512 = 16 warps laid out 4(M) x 4(N)
__global__ void __launch_bounds__(512, 1) fused_kernel(
    const float* __restrict__ bz, const float* __restrict__ bh,
    const float* __restrict__ h0g, float* __restrict__ out)
{
    extern __shared__ char smem[];
    const uint32_t sbase = smem_u32(smem);

    float*   segP = reinterpret_cast<float*>(smem + SM_SEGP);
    float*   segS = reinterpret_cast<float*>(smem + SM_SEGS);
    float*   hcF  = reinterpret_cast<float*>(smem + SM_HC);
    __half2* scvH = reinterpret_cast<__half2*>(smem + SM_CV);
    uint32_t* scvU = reinterpret_cast<uint32_t*>(smem + SM_CV);

    const int tid  = threadIdx.x;
    const int lane = tid & 31;
    const int wid  = tid >> 5;
    const int wm   = wid >> 2;    // 0..3 (token dir, 32 rows each)
    const int wn   = wid & 3;     // 0..3 (h dir, 16 cols each)
    const int grp  = lane >> 2;   // 0..7
    const int tg   = lane & 3;    // 0..3
    const int lrow = ((lane >> 3) & 1) * 8 + (lane & 7);
    const int lkh  = (lane >> 4) * 16;

    const int slice = blockIdx.x;
    const int b     = blockIdx.y;
    const int hbase = slice * HSL;

    // scan-phase mapping
    const int seg = tid >> 6;      // 0..7, 16 tokens each
    const int hch = tid & 63;      // h channel within slice

    // init h carry
    if (tid < HSL) hcF[tid] = g_act(h0g[b * H_ + hbase + tid]);

    // bias preload
    float bzr[2][2], bhr[2][2];
    #pragma unroll
    for (int nt = 0; nt < 2; nt++) {
        int col = hbase + wn * 16 + nt * 8 + 2 * tg;
        bzr[nt][0] = bz[col];     bzr[nt][1] = bz[col + 1];
        bhr[nt][0] = bh[col];     bhr[nt][1] = bh[col + 1];
    }

    const uint4* Xh4  = reinterpret_cast<const uint4*>(g_Xh);
    const uint4* Wzh4 = reinterpret_cast<const uint4*>(g_Wzh);
    const uint4* Whh4 = reinterpret_cast<const uint4*>(g_Whh);

    auto ld_A = [&](int s) {
        const uint32_t sb = sbase + SM_A + (s & 3) * 16384;
        const size_t tok0 = (size_t)b * T_ + (size_t)(s >> 2) * TCH;
        const int kc = s & 3;
        #pragma unroll
        for (int i = 0; i < 2; i++) {
            int q = tid + i * 512;
            int r = q >> 3, u = q & 7;
            cp16(sb + SWZ(r * 128 + u * 16), Xh4 + (tok0 + r) * 32 + kc * 8 + u);
        }
    };
    auto ld_W = [&]() {
        #pragma unroll
        for (int i = 0; i < 8; i++) {
            int q = tid + i * 512;
            int c = q >> 10, rem = q & 1023;
            int r = rem >> 3, u = rem & 7;
            const uint4* src = (r < 64) ? (Wzh4 + (size_t)(hbase + r) * 32 + c * 8 + u)
                                        : (Whh4 + (size_t)(hbase + r - 64) * 32 + c * 8 + u);
            cp16(sbase + SM_W + c * 16384 + SWZ(r * 128 + u * 16), src);
        }
    };

    float accZ[2][2][4], accH[2][2][4];
    #pragma unroll
    for (int mt = 0; mt < 2; mt++)
        #pragma unroll
        for (int nt = 0; nt < 2; nt++)
            #pragma unroll
            for (int q = 0; q < 4; q++) { accZ[mt][nt][q] = 0.f; accH[mt][nt][q] = 0.f; }

    ld_W(); ld_A(0); CP_COMMIT();
    ld_A(1); CP_COMMIT();
    ld_A(2); CP_COMMIT();

    #pragma unroll 1
    for (int s = 0; s < NSTG; s++) {
        CP_WAIT2();            // group s complete (<=2 younger pending)
        __syncthreads();

        if (s + 3 < NSTG) { ld_A(s + 3); CP_COMMIT(); }
        else              { CP_COMMIT(); }   // dummy: uniform group count

        const uint32_t aBase = sbase + SM_A + (s & 3) * 16384;
        const uint32_t wBase = sbase + SM_W + (s & 3) * 16384;

        // fragment double-buffering across the ks loop
        uint32_t fa[2][2][4], fz[2][4], fh[2][4];
        {
            const int kb = lkh;
            #pragma unroll
            for (int mt = 0; mt < 2; mt++)
                ldm_x4(fa[0][mt][0], fa[0][mt][1], fa[0][mt][2], fa[0][mt][3],
                       aBase + SWZ((wm * 32 + mt * 16 + lrow) * 128 + kb));
            ldm_x4(fz[0][0], fz[0][1], fz[0][2], fz[0][3],
                   wBase + SWZ((wn * 16 + lrow) * 128 + kb));
            ldm_x4(fh[0][0], fh[0][1], fh[0][2], fh[0][3],
                   wBase + SWZ((64 + wn * 16 + lrow) * 128 + kb));
        }
        #pragma unroll
        for (int ks = 0; ks < KC / 16; ks++) {
            const int cur = ks & 1;
            if (ks + 1 < KC / 16) {
                const int nxt = cur ^ 1;
                const int kb = (ks + 1) * 32 + lkh;
                #pragma unroll
                for (int mt = 0; mt < 2; mt++)
                    ldm_x4(fa[nxt][mt][0], fa[nxt][mt][1], fa[nxt][mt][2], fa[nxt][mt][3],
                           aBase + SWZ((wm * 32 + mt * 16 + lrow) * 128 + kb));
                ldm_x4(fz[nxt][0], fz[nxt][1], fz[nxt][2], fz[nxt][3],
                       wBase + SWZ((wn * 16 + lrow) * 128 + kb));
                ldm_x4(fh[nxt][0], fh[nxt][1], fh[nxt][2], fh[nxt][3],
                       wBase + SWZ((64 + wn * 16 + lrow) * 128 + kb));
            }
            #pragma unroll
            for (int mt = 0; mt < 2; mt++)
                #pragma unroll
                for (int nt = 0; nt < 2; nt++) {
                    mma_f16(accZ[mt][nt], fa[cur][mt], fz[cur][nt], fz[cur][nt + 2]);
                    mma_f16(accH[mt][nt], fa[cur][mt], fh[cur][nt], fh[cur][nt + 2]);
                }
        }

        if ((s & 3) == 3) {
            const int chunk = s >> 2;

            // ---- activation -> cv smem ----
            #pragma unroll
            for (int mt = 0; mt < 2; mt++) {
                #pragma unroll
                for (int nt = 0; nt < 2; nt++) {
                    const int col = wn * 16 + nt * 8 + 2 * tg;   // local h
                    const int r0  = wm * 32 + mt * 16 + grp;     // local token
                    float k0  = accZ[mt][nt][0] + bzr[nt][0];
                    float k1  = accZ[mt][nt][1] + bzr[nt][1];
                    float k2  = accZ[mt][nt][2] + bzr[nt][0];
                    float k3  = accZ[mt][nt][3] + bzr[nt][1];
                    float kh0 = accH[mt][nt][0] + bhr[nt][0];
                    float kh1 = accH[mt][nt][1] + bhr[nt][1];
                    float kh2 = accH[mt][nt][2] + bhr[nt][0];
                    float kh3 = accH[mt][nt][3] + bhr[nt][1];
                    float z0 = sigmoid_f(k0), z1 = sigmoid_f(k1);
                    float z2 = sigmoid_f(k2), z3 = sigmoid_f(k3);
                    uint2 p0 = make_uint2(pack_cv(1.f - z0, z0 * g_act(kh0)),
                                          pack_cv(1.f - z1, z1 * g_act(kh1)));
                    uint2 p1 = make_uint2(pack_cv(1.f - z2, z2 * g_act(kh2)),
                                          pack_cv(1.f - z3, z3 * g_act(kh3)));
                    *reinterpret_cast<uint2*>(&scvU[CVIDX(r0,     col)]) = p0;
                    *reinterpret_cast<uint2*>(&scvU[CVIDX(r0 + 8, col)]) = p1;
                }
            }
            __syncthreads();

            // ---- segment aggregate (16 tokens per thread) ----
            float P = 1.f, S = 0.f;
            const int tokb = seg * 16;
            #pragma unroll
            for (int j = 0; j < 16; j++) {
                float2 cv = __half22float2(scvH[CVIDX(tokb + j, hch)]);
                S = fmaf(cv.x, S, cv.y);
                P *= cv.x;
            }
            segP[seg * 64 + hch] = P;
            segS[seg * 64 + hch] = S;
            __syncthreads();

            // ---- combine: prefix over segments + carry ----
            float hin = hcF[hch];
            #pragma unroll
            for (int q = 0; q < 7; q++)
                if (q < seg) hin = fmaf(segP[q * 64 + hch], hin, segS[q * 64 + hch]);
            __syncthreads();   // all carry reads done before seg7 overwrites

            // ---- replay + emit ----
            float hv = hin;
            size_t obase = ((size_t)b * T_ + (size_t)chunk * TCH + tokb) * H_ + hbase + hch;
            #pragma unroll
            for (int j = 0; j < 16; j++) {
                float2 cv = __half22float2(scvH[CVIDX(tokb + j, hch)]);
                hv = fmaf(cv.x, hv, cv.y);
                out[obase + (size_t)j * H_] = hv;
            }
            if (seg == 7) hcF[hch] = hv;
            __syncthreads();

            // reset accumulators
            #pragma unroll
            for (int mt = 0; mt < 2; mt++)
                #pragma unroll
                for (int nt = 0; nt < 2; nt++)
                    #pragma unroll
                    for (int q = 0; q < 4; q++) { accZ[mt][nt][q] = 0.f; accH[mt][nt][q] = 0.f; }
        }
    }
}

// ---------------- launch -------------------------------------------------
extern "C" void kernel_launch(void* const* d_in, const int* in_sizes, int n_in,
                              void* d_out, int out_size)
{
    const float* x  = (const float*)d_in[0];
    const float* h0 = (const float*)d_in[1];
    const float* Wz = (const float*)d_in[2];
    const float* bz = (const float*)d_in[3];
    const float* Wh = (const float*)d_in[4];
    const float* bh = (const float*)d_in[5];
    float* out = (float*)d_out;

    convert_kernel<<<512, 256>>>(x, Wz, Wh);

    cudaFuncSetAttribute(fused_kernel, cudaFuncAttributeMaxDynamicSharedMemorySize, SMEM_FUSED);
    dim3 fgrid(H_ / HSL, B_);            // (4, 32) = 128 CTAs
    fused_kernel<<<fgrid, 512, SMEM_FUSED>>>(bz, bh, h0, out);
}

// round 12
// speedup vs baseline: 1.1920x; 1.0263x over previous
#include <cuda_runtime.h>
#include <cuda_fp16.h>
#include <cstdint>

// ---------------- problem dims ----------------
#define B_   32
#define T_   4096
#define DIN_ 256
#define H_   256
#define BT_  (B_ * T_)

// ---------------- fused tiling ------------------
#define TCH   128             // tokens per chunk
#define NCHK  (T_ / TCH)      // 32 chunks
#define KC    64              // K halves per k-stage (128B rows)
#define NKC   (DIN_ / KC)     // 4 k-stages per chunk
#define NSTG  (NCHK * NKC)    // 128 total k-stages
#define HSL   64              // h channels per CTA slice

// smem layout (bytes)
#define SM_A     0                  // 2 stages x 16384 (A: 128 tok x 64 halves, fp16)
#define SM_W     32768              // 4 panels x 16384 (W: 64 z-rows + 64 h-rows x 64 halves)
#define SM_CV    98304              // 128 tok x 64 h x half2 = 32768
#define SM_SEGP  131072             // 8 x 64 floats
#define SM_SEGS  133120             // 8 x 64 floats
#define SM_HC    135168             // 64 floats carry
#define SMEM_FUSED 135424

// cv smem swizzle: word index for (token t, channel h)
#define CVIDX(t, h) ((t) * 64 + ((h) ^ (((t) & 7) << 3)))

// ---------------- helpers ------------------
__device__ __forceinline__ uint32_t smem_u32(const void* p) {
    uint32_t r;
    asm("{\n\t.reg .u64 t;\n\tcvta.to.shared.u64 t, %1;\n\tcvt.u32.u64 %0, t;\n\t}"
        : "=r"(r) : "l"(p));
    return r;
}
#define SWZ(o) ((o) ^ ((((uint32_t)(o)) >> 3) & 0x70))

__device__ __forceinline__ void ldm_x4(uint32_t& r0, uint32_t& r1, uint32_t& r2, uint32_t& r3,
                                       uint32_t addr) {
    asm volatile("ldmatrix.sync.aligned.m8n8.x4.shared.b16 {%0,%1,%2,%3}, [%4];"
                 : "=r"(r0), "=r"(r1), "=r"(r2), "=r"(r3) : "r"(addr));
}
__device__ __forceinline__ void mma_f16(float* d, const uint32_t* a, uint32_t b0, uint32_t b1) {
    asm volatile("mma.sync.aligned.m16n8k16.row.col.f32.f16.f16.f32 "
                 "{%0,%1,%2,%3}, {%4,%5,%6,%7}, {%8,%9}, {%0,%1,%2,%3};"
                 : "+f"(d[0]), "+f"(d[1]), "+f"(d[2]), "+f"(d[3])
                 : "r"(a[0]), "r"(a[1]), "r"(a[2]), "r"(a[3]), "r"(b0), "r"(b1));
}

__device__ __forceinline__ float sigmoid_f(float x) {
    return __fdividef(1.f, 1.f + __expf(-x));
}
__device__ __forceinline__ float g_act(float x) {
    return x >= 0.f ? x + 0.5f : sigmoid_f(x);
}
__device__ __forceinline__ uint32_t pack_h2(float a, float b) {
    __half2 p = __floats2half2_rn(a, b);
    return *reinterpret_cast<uint32_t*>(&p);
}

// ---------------- fused convert + GEMM + activation + scan ----------------
// grid: (slice [0,4), batch [0,32)); block 512 = 16 warps laid out 4(M) x 4(N)
__global__ void __launch_bounds__(512, 1) fused_kernel(
    const float* __restrict__ X,
    const float* __restrict__ Wz, const float* __restrict__ bz,
    const float* __restrict__ Wh, const float* __restrict__ bh,
    const float* __restrict__ h0g, float* __restrict__ out)
{
    extern __shared__ char smem[];
    const uint32_t sbase = smem_u32(smem);

    float*   segP = reinterpret_cast<float*>(smem + SM_SEGP);
    float*   segS = reinterpret_cast<float*>(smem + SM_SEGS);
    float*   hcF  = reinterpret_cast<float*>(smem + SM_HC);
    __half2* scvH = reinterpret_cast<__half2*>(smem + SM_CV);
    uint32_t* scvU = reinterpret_cast<uint32_t*>(smem + SM_CV);

    const int tid  = threadIdx.x;
    const int lane = tid & 31;
    const int wid  = tid >> 5;
    const int wm   = wid >> 2;    // 0..3 (token dir, 32 rows each)
    const int wn   = wid & 3;     // 0..3 (h dir, 16 cols each)
    const int grp  = lane >> 2;   // 0..7
    const int tg   = lane & 3;    // 0..3
    const int lrow = ((lane >> 3) & 1) * 8 + (lane & 7);
    const int lkh  = (lane >> 4) * 16;

    const int slice = blockIdx.x;
    const int b     = blockIdx.y;
    const int hbase = slice * HSL;

    // scan-phase mapping
    const int seg = tid >> 6;      // 0..7, 16 tokens each
    const int hch = tid & 63;      // h channel within slice

    // init h carry
    if (tid < HSL) hcF[tid] = g_act(h0g[b * H_ + hbase + tid]);

    // bias preload
    float bzr[2][2], bhr[2][2];
    #pragma unroll
    for (int nt = 0; nt < 2; nt++) {
        int col = hbase + wn * 16 + nt * 8 + 2 * tg;
        bzr[nt][0] = bz[col];     bzr[nt][1] = bz[col + 1];
        bhr[nt][0] = bh[col];     bhr[nt][1] = bh[col + 1];
    }

    const float4* X4f  = reinterpret_cast<const float4*>(X);
    const float4* Wz4f = reinterpret_cast<const float4*>(Wz);
    const float4* Wh4f = reinterpret_cast<const float4*>(Wh);

    // ---- prologue: convert this CTA's W slice fp32 -> fp16 swizzled smem ----
    // 4 panels x 128 rows (64 z + 64 h) x 8 16B-units = 4096 units / 512 thr = 8 each
    #pragma unroll
    for (int i = 0; i < 8; i++) {
        int q = tid + i * 512;
        int c = q >> 10, rem = q & 1023;
        int r = rem >> 3, u = rem & 7;
        const float4* src = (r < 64) ? (Wz4f + (size_t)(hbase + r) * 64 + c * 16 + u * 2)
                                     : (Wh4f + (size_t)(hbase + r - 64) * 64 + c * 16 + u * 2);
        float4 f0 = src[0], f1 = src[1];
        uint4 o = make_uint4(pack_h2(f0.x, f0.y), pack_h2(f0.z, f0.w),
                             pack_h2(f1.x, f1.y), pack_h2(f1.z, f1.w));
        *reinterpret_cast<uint4*>(smem + SM_W + c * 16384 + SWZ(r * 128 + u * 16)) = o;
    }

    // ---- A staging: LDG fp32 -> regs -> (next boundary) cvt+STS fp16 ----
    // per stage: 128 rows x 8 units = 1024 units / 512 thr = 2 each
    const int arQ0 = tid, arQ1 = tid + 512;
    const int arR0 = arQ0 >> 3, arU0 = arQ0 & 7;
    const int arR1 = arQ1 >> 3, arU1 = arQ1 & 7;
    float4 areg[2][2];

    auto load_A = [&](int s) {
        const size_t tok0 = (size_t)b * T_ + (size_t)(s >> 2) * TCH;
        const int kc = s & 3;
        areg[0][0] = X4f[(tok0 + arR0) * 64 + kc * 16 + arU0 * 2];
        areg[0][1] = X4f[(tok0 + arR0) * 64 + kc * 16 + arU0 * 2 + 1];
        areg[1][0] = X4f[(tok0 + arR1) * 64 + kc * 16 + arU1 * 2];
        areg[1][1] = X4f[(tok0 + arR1) * 64 + kc * 16 + arU1 * 2 + 1];
    };
    auto sts_A = [&](int s) {
        char* sb = smem + SM_A + (s & 1) * 16384;
        uint4 o0 = make_uint4(pack_h2(areg[0][0].x, areg[0][0].y), pack_h2(areg[0][0].z, areg[0][0].w),
                              pack_h2(areg[0][1].x, areg[0][1].y), pack_h2(areg[0][1].z, areg[0][1].w));
        *reinterpret_cast<uint4*>(sb + SWZ(arR0 * 128 + arU0 * 16)) = o0;
        uint4 o1 = make_uint4(pack_h2(areg[1][0].x, areg[1][0].y), pack_h2(areg[1][0].z, areg[1][0].w),
                              pack_h2(areg[1][1].x, areg[1][1].y), pack_h2(areg[1][1].z, areg[1][1].w));
        *reinterpret_cast<uint4*>(sb + SWZ(arR1 * 128 + arU1 * 16)) = o1;
    };

    float accZ[2][2][4], accH[2][2][4];
    #pragma unroll
    for (int mt = 0; mt < 2; mt++)
        #pragma unroll
        for (int nt = 0; nt < 2; nt++)
            #pragma unroll
            for (int q = 0; q < 4; q++) { accZ[mt][nt][q] = 0.f; accH[mt][nt][q] = 0.f; }

    load_A(0);
    sts_A(0);          // scoreboard orders STS after the LDGs
    load_A(1);
    __syncthreads();   // W prologue + A0 visible to all

    #pragma unroll 1
    for (int s = 0; s < NSTG; s++) {
        const uint32_t aBase = sbase + SM_A + (s & 1) * 16384;
        const uint32_t wBase = sbase + SM_W + (s & 3) * 16384;

        #pragma unroll
        for (int ks = 0; ks < KC / 16; ks++) {
            const int kb = ks * 32 + lkh;
            uint32_t a[2][4], z[4], hh[4];
            #pragma unroll
            for (int mt = 0; mt < 2; mt++)
                ldm_x4(a[mt][0], a[mt][1], a[mt][2], a[mt][3],
                       aBase + SWZ((wm * 32 + mt * 16 + lrow) * 128 + kb));
            ldm_x4(z[0], z[1], z[2], z[3],
                   wBase + SWZ((wn * 16 + lrow) * 128 + kb));
            ldm_x4(hh[0], hh[1], hh[2], hh[3],
                   wBase + SWZ((64 + wn * 16 + lrow) * 128 + kb));
            #pragma unroll
            for (int mt = 0; mt < 2; mt++)
                #pragma unroll
                for (int nt = 0; nt < 2; nt++) {
                    mma_f16(accZ[mt][nt], a[mt], z[nt], z[nt + 2]);
                    mma_f16(accH[mt][nt], a[mt], hh[nt], hh[nt + 2]);
                }
        }

        if ((s & 3) == 3) {
            const int chunk = s >> 2;

            // ---- activation -> cv smem ----
            #pragma unroll
            for (int mt = 0; mt < 2; mt++) {
                #pragma unroll
                for (int nt = 0; nt < 2; nt++) {
                    const int col = wn * 16 + nt * 8 + 2 * tg;   // local h
                    const int r0  = wm * 32 + mt * 16 + grp;     // local token
                    float k0  = accZ[mt][nt][0] + bzr[nt][0];
                    float k1  = accZ[mt][nt][1] + bzr[nt][1];
                    float k2  = accZ[mt][nt][2] + bzr[nt][0];
                    float k3  = accZ[mt][nt][3] + bzr[nt][1];
                    float kh0 = accH[mt][nt][0] + bhr[nt][0];
                    float kh1 = accH[mt][nt][1] + bhr[nt][1];
                    float kh2 = accH[mt][nt][2] + bhr[nt][0];
                    float kh3 = accH[mt][nt][3] + bhr[nt][1];
                    float z0 = sigmoid_f(k0), z1 = sigmoid_f(k1);
                    float z2 = sigmoid_f(k2), z3 = sigmoid_f(k3);
                    uint2 p0 = make_uint2(pack_h2(1.f - z0, z0 * g_act(kh0)),
                                          pack_h2(1.f - z1, z1 * g_act(kh1)));
                    uint2 p1 = make_uint2(pack_h2(1.f - z2, z2 * g_act(kh2)),
                                          pack_h2(1.f - z3, z3 * g_act(kh3)));
                    *reinterpret_cast<uint2*>(&scvU[CVIDX(r0,     col)]) = p0;
                    *reinterpret_cast<uint2*>(&scvU[CVIDX(r0 + 8, col)]) = p1;
                }
            }
            __syncthreads();

            // ---- segment aggregate (16 tokens per thread) ----
            float P = 1.f, S = 0.f;
            const int tokb = seg * 16;
            #pragma unroll
            for (int j = 0; j < 16; j++) {
                float2 cv = __half22float2(scvH[CVIDX(tokb + j, hch)]);
                S = fmaf(cv.x, S, cv.y);
                P *= cv.x;
            }
            segP[seg * 64 + hch] = P;
            segS[seg * 64 + hch] = S;
            __syncthreads();

            // ---- combine: prefix over segments + carry ----
            float hin = hcF[hch];
            #pragma unroll
            for (int q = 0; q < 7; q++)
                if (q < seg) hin = fmaf(segP[q * 64 + hch], hin, segS[q * 64 + hch]);
            __syncthreads();   // all carry reads done before seg7 overwrites

            // ---- replay + emit ----
            float hv = hin;
            size_t obase = ((size_t)b * T_ + (size_t)chunk * TCH + tokb) * H_ + hbase + hch;
            #pragma unroll
            for (int j = 0; j < 16; j++) {
                float2 cv = __half22float2(scvH[CVIDX(tokb + j, hch)]);
                hv = fmaf(cv.x, hv, cv.y);
                out[obase + (size_t)j * H_] = hv;
            }
            if (seg == 7) hcF[hch] = hv;
            __syncthreads();

            // reset accumulators
            #pragma unroll
            for (int mt = 0; mt < 2; mt++)
                #pragma unroll
                for (int nt = 0; nt < 2; nt++)
                    #pragma unroll
                    for (int q = 0; q < 4; q++) { accZ[mt][nt][q] = 0.f; accH[mt][nt][q] = 0.f; }
        }

        // ---- stage the next A tiles ----
        if (s + 1 < NSTG) sts_A(s + 1);     // writes buf (s+1)&1, safe vs compute(s)
        if (s + 2 < NSTG) load_A(s + 2);    // LDG latency covered by stage s+1
        __syncthreads();
    }
}

// ---------------- launch -------------------------------------------------
extern "C" void kernel_launch(void* const* d_in, const int* in_sizes, int n_in,
                              void* d_out, int out_size)
{
    const float* x  = (const float*)d_in[0];
    const float* h0 = (const float*)d_in[1];
    const float* Wz = (const float*)d_in[2];
    const float* bz = (const float*)d_in[3];
    const float* Wh = (const float*)d_in[4];
    const float* bh = (const float*)d_in[5];
    float* out = (float*)d_out;

    cudaFuncSetAttribute(fused_kernel, cudaFuncAttributeMaxDynamicSharedMemorySize, SMEM_FUSED);
    dim3 fgrid(H_ / HSL, B_);            // (4, 32) = 128 CTAs
    fused_kernel<<<fgrid, 512, SMEM_FUSED>>>(x, Wz, bz, Wh, bh, h0, out);
}

// round 14
// speedup vs baseline: 1.2288x; 1.0308x over previous
#include <cuda_runtime.h>
#include <cuda_fp16.h>
#include <cstdint>

// ---------------- problem dims ----------------
#define B_   32
#define T_   4096
#define DIN_ 256
#define H_   256
#define BT_  (B_ * T_)

// ---------------- fused tiling ------------------
#define TCH   128             // tokens per chunk
#define NCHK  (T_ / TCH)      // 32 chunks
#define HSL   64              // h channels per CTA slice

// smem layout (bytes)
#define SM_A     0                  // 4 K-panels x 16384 (full chunk: 128 tok x 256 halves)
#define SM_W     65536              // 4 K-panels x 16384 (W: 64 z-rows + 64 h-rows)
#define SM_CV    131072             // 128 tok x 64 h x half2 = 32768
#define SM_SEGP  163840             // 8 x 64 floats
#define SM_SEGS  165888             // 8 x 64 floats
#define SM_HC    167936             // 64 floats carry
#define SMEM_FUSED 168192

// cv smem swizzle: word index for (token t, channel h)
#define CVIDX(t, h) ((t) * 64 + ((h) ^ (((t) & 7) << 3)))

// ---------------- scratch ----------------------
__device__ __half g_Xh[(size_t)BT_ * DIN_];

// ---------------- fp32 -> fp16 convert (X only) ----------------
__global__ void __launch_bounds__(256) convert_kernel(const float* __restrict__ X)
{
    const size_t i = (size_t)blockIdx.x * blockDim.x + threadIdx.x;
    const size_t stride = (size_t)gridDim.x * blockDim.x;
    const size_t XF4 = (size_t)BT_ * DIN_ / 4;

    const float4* X4 = reinterpret_cast<const float4*>(X);
    uint2* OX = reinterpret_cast<uint2*>(g_Xh);
    for (size_t j = i; j < XF4; j += stride) {
        float4 v = X4[j];
        __half2 h0 = __floats2half2_rn(v.x, v.y);
        __half2 h1 = __floats2half2_rn(v.z, v.w);
        OX[j] = make_uint2(*reinterpret_cast<uint32_t*>(&h0), *reinterpret_cast<uint32_t*>(&h1));
    }
}

// ---------------- helpers ------------------
__device__ __forceinline__ uint32_t smem_u32(const void* p) {
    uint32_t r;
    asm("{\n\t.reg .u64 t;\n\tcvta.to.shared.u64 t, %1;\n\tcvt.u32.u64 %0, t;\n\t}"
        : "=r"(r) : "l"(p));
    return r;
}
__device__ __forceinline__ void cp16(uint32_t dst, const void* src) {
    asm volatile("cp.async.cg.shared.global [%0], [%1], 16;" :: "r"(dst), "l"(src));
}
#define CP_COMMIT()  asm volatile("cp.async.commit_group;" ::: "memory")
#define CP_WAIT0()   asm volatile("cp.async.wait_group 0;" ::: "memory")
#define SWZ(o) ((o) ^ ((((uint32_t)(o)) >> 3) & 0x70))

__device__ __forceinline__ void ldm_x4(uint32_t& r0, uint32_t& r1, uint32_t& r2, uint32_t& r3,
                                       uint32_t addr) {
    asm volatile("ldmatrix.sync.aligned.m8n8.x4.shared.b16 {%0,%1,%2,%3}, [%4];"
                 : "=r"(r0), "=r"(r1), "=r"(r2), "=r"(r3) : "r"(addr));
}
__device__ __forceinline__ void mma_f16(float* d, const uint32_t* a, uint32_t b0, uint32_t b1) {
    asm volatile("mma.sync.aligned.m16n8k16.row.col.f32.f16.f16.f32 "
                 "{%0,%1,%2,%3}, {%4,%5,%6,%7}, {%8,%9}, {%0,%1,%2,%3};"
                 : "+f"(d[0]), "+f"(d[1]), "+f"(d[2]), "+f"(d[3])
                 : "r"(a[0]), "r"(a[1]), "r"(a[2]), "r"(a[3]), "r"(b0), "r"(b1));
}

__device__ __forceinline__ float sigmoid_f(float x) {
    return __fdividef(1.f, 1.f + __expf(-x));
}
__device__ __forceinline__ float g_act(float x) {
    return x >= 0.f ? x + 0.5f : sigmoid_f(x);
}
__device__ __forceinline__ uint32_t pack_h2(float a, float b) {
    __half2 p = __floats2half2_rn(a, b);
    return *reinterpret_cast<uint32_t*>(&p);
}

// ---------------- fused GEMM + activation + scan ----------------
// grid: (slice [0,4), batch [0,32)); block 512 = 16 warps laid out 4(M) x 4(N)
__global__ void __launch_bounds__(512, 1) fused_kernel(
    const float* __restrict__ Wz, const float* __restrict__ bz,
    const float* __restrict__ Wh, const float* __restrict__ bh,
    const float* __restrict__ h0g, float* __restrict__ out)
{
    extern __shared__ char smem[];
    const uint32_t sbase = smem_u32(smem);

    float*   segP = reinterpret_cast<float*>(smem + SM_SEGP);
    float*   segS = reinterpret_cast<float*>(smem + SM_SEGS);
    float*   hcF  = reinterpret_cast<float*>(smem + SM_HC);
    __half2* scvH = reinterpret_cast<__half2*>(smem + SM_CV);
    uint32_t* scvU = reinterpret_cast<uint32_t*>(smem + SM_CV);

    const int tid  = threadIdx.x;
    const int lane = tid & 31;
    const int wid  = tid >> 5;
    const int wm   = wid >> 2;    // 0..3 (token dir, 32 rows each)
    const int wn   = wid & 3;     // 0..3 (h dir, 16 cols each)
    const int grp  = lane >> 2;   // 0..7
    const int tg   = lane & 3;    // 0..3
    const int lrow = ((lane >> 3) & 1) * 8 + (lane & 7);
    const int lkh  = (lane >> 4) * 16;

    const int slice = blockIdx.x;
    const int b     = blockIdx.y;
    const int hbase = slice * HSL;

    // scan-phase mapping
    const int seg = tid >> 6;      // 0..7, 16 tokens each
    const int hch = tid & 63;      // h channel within slice

    // init h carry
    if (tid < HSL) hcF[tid] = g_act(h0g[b * H_ + hbase + tid]);

    // bias preload
    float bzr[2][2], bhr[2][2];
    #pragma unroll
    for (int nt = 0; nt < 2; nt++) {
        int col = hbase + wn * 16 + nt * 8 + 2 * tg;
        bzr[nt][0] = bz[col];     bzr[nt][1] = bz[col + 1];
        bhr[nt][0] = bh[col];     bhr[nt][1] = bh[col + 1];
    }

    const float4* Wz4f = reinterpret_cast<const float4*>(Wz);
    const float4* Wh4f = reinterpret_cast<const float4*>(Wh);
    const uint4*  Xh16 = reinterpret_cast<const uint4*>(g_Xh);

    // ---- prologue: convert this CTA's W slice fp32 -> fp16 swizzled smem ----
    #pragma unroll
    for (int i = 0; i < 8; i++) {
        int q = tid + i * 512;
        int c = q >> 10, rem = q & 1023;
        int r = rem >> 3, u = rem & 7;
        const float4* src = (r < 64) ? (Wz4f + (size_t)(hbase + r) * 64 + c * 16 + u * 2)
                                     : (Wh4f + (size_t)(hbase + r - 64) * 64 + c * 16 + u * 2);
        float4 f0 = src[0], f1 = src[1];
        uint4 o = make_uint4(pack_h2(f0.x, f0.y), pack_h2(f0.z, f0.w),
                             pack_h2(f1.x, f1.y), pack_h2(f1.z, f1.w));
        *reinterpret_cast<uint4*>(smem + SM_W + c * 16384 + SWZ(r * 128 + u * 16)) = o;
    }

    // ---- chunk loader: full 128 tok x 256 halves (64KB) via cp.async ----
    auto ld_chunk = [&](int c) {
        const size_t tok0 = (size_t)b * T_ + (size_t)c * TCH;
        #pragma unroll
        for (int i = 0; i < 8; i++) {
            int q = tid + i * 512;          // 0..4095
            int r = q >> 5;                 // token row 0..127
            int u = q & 31;                 // 16B unit within 512B row
            int p = u >> 3, uu = u & 7;     // K-panel, unit within panel
            cp16(sbase + SM_A + p * 16384 + SWZ(r * 128 + uu * 16),
                 Xh16 + (tok0 + r) * 32 + u);
        }
    };

    float accZ[2][2][4], accH[2][2][4];
    #pragma unroll
    for (int mt = 0; mt < 2; mt++)
        #pragma unroll
        for (int nt = 0; nt < 2; nt++)
            #pragma unroll
            for (int q = 0; q < 4; q++) { accZ[mt][nt][q] = 0.f; accH[mt][nt][q] = 0.f; }

    ld_chunk(0); CP_COMMIT();
    CP_WAIT0();
    __syncthreads();   // W prologue + chunk 0 visible

    #pragma unroll 1
    for (int chunk = 0; chunk < NCHK; chunk++) {
        // ---- GEMM: full chunk, 16 uninterrupted ks iterations ----
        #pragma unroll
        for (int ks = 0; ks < 16; ks++) {
            const uint32_t aB = sbase + SM_A + (ks >> 2) * 16384;
            const uint32_t wB = sbase + SM_W + (ks >> 2) * 16384;
            const int kb = (ks & 3) * 32 + lkh;
            uint32_t a[2][4], z[4], hh[4];
            #pragma unroll
            for (int mt = 0; mt < 2; mt++)
                ldm_x4(a[mt][0], a[mt][1], a[mt][2], a[mt][3],
                       aB + SWZ((wm * 32 + mt * 16 + lrow) * 128 + kb));
            ldm_x4(z[0], z[1], z[2], z[3],
                   wB + SWZ((wn * 16 + lrow) * 128 + kb));
            ldm_x4(hh[0], hh[1], hh[2], hh[3],
                   wB + SWZ((64 + wn * 16 + lrow) * 128 + kb));
            #pragma unroll
            for (int mt = 0; mt < 2; mt++)
                #pragma unroll
                for (int nt = 0; nt < 2; nt++) {
                    mma_f16(accZ[mt][nt], a[mt], z[nt], z[nt + 2]);
                    mma_f16(accH[mt][nt], a[mt], hh[nt], hh[nt + 2]);
                }
        }

        // ---- activation -> cv smem ----
        #pragma unroll
        for (int mt = 0; mt < 2; mt++) {
            #pragma unroll
            for (int nt = 0; nt < 2; nt++) {
                const int col = wn * 16 + nt * 8 + 2 * tg;   // local h
                const int r0  = wm * 32 + mt * 16 + grp;     // local token
                float k0  = accZ[mt][nt][0] + bzr[nt][0];
                float k1  = accZ[mt][nt][1] + bzr[nt][1];
                float k2  = accZ[mt][nt][2] + bzr[nt][0];
                float k3  = accZ[mt][nt][3] + bzr[nt][1];
                float kh0 = accH[mt][nt][0] + bhr[nt][0];
                float kh1 = accH[mt][nt][1] + bhr[nt][1];
                float kh2 = accH[mt][nt][2] + bhr[nt][0];
                float kh3 = accH[mt][nt][3] + bhr[nt][1];
                float z0 = sigmoid_f(k0), z1 = sigmoid_f(k1);
                float z2 = sigmoid_f(k2), z3 = sigmoid_f(k3);
                uint2 p0 = make_uint2(pack_h2(1.f - z0, z0 * g_act(kh0)),
                                      pack_h2(1.f - z1, z1 * g_act(kh1)));
                uint2 p1 = make_uint2(pack_h2(1.f - z2, z2 * g_act(kh2)),
                                      pack_h2(1.f - z3, z3 * g_act(kh3)));
                *reinterpret_cast<uint2*>(&scvU[CVIDX(r0,     col)]) = p0;
                *reinterpret_cast<uint2*>(&scvU[CVIDX(r0 + 8, col)]) = p1;
            }
        }
        __syncthreads();   // all GEMM A-reads done + cv visible

        // ---- prefetch next chunk; fill overlaps the scan phase ----
        if (chunk + 1 < NCHK) { ld_chunk(chunk + 1); CP_COMMIT(); }

        // ---- segment aggregate (16 tokens per thread) ----
        float P = 1.f, S = 0.f;
        const int tokb = seg * 16;
        #pragma unroll
        for (int j = 0; j < 16; j++) {
            float2 cv = __half22float2(scvH[CVIDX(tokb + j, hch)]);
            S = fmaf(cv.x, S, cv.y);
            P *= cv.x;
        }
        segP[seg * 64 + hch] = P;
        segS[seg * 64 + hch] = S;
        __syncthreads();

        // ---- combine: prefix over segments + carry ----
        float hin = hcF[hch];
        #pragma unroll
        for (int q = 0; q < 7; q++)
            if (q < seg) hin = fmaf(segP[q * 64 + hch], hin, segS[q * 64 + hch]);
        __syncthreads();   // all carry reads done before seg7 overwrites

        // ---- replay + emit ----
        float hv = hin;
        size_t obase = ((size_t)b * T_ + (size_t)chunk * TCH + tokb) * H_ + hbase + hch;
        #pragma unroll
        for (int j = 0; j < 16; j++) {
            float2 cv = __half22float2(scvH[CVIDX(tokb + j, hch)]);
            hv = fmaf(cv.x, hv, cv.y);
            out[obase + (size_t)j * H_] = hv;
        }
        if (seg == 7) hcF[hch] = hv;

        CP_WAIT0();        // next chunk's A resident
        __syncthreads();   // hcF/cv/segP reuse safe + A visible

        // reset accumulators
        #pragma unroll
        for (int mt = 0; mt < 2; mt++)
            #pragma unroll
            for (int nt = 0; nt < 2; nt++)
                #pragma unroll
                for (int q = 0; q < 4; q++) { accZ[mt][nt][q] = 0.f; accH[mt][nt][q] = 0.f; }
    }
}

// ---------------- launch -------------------------------------------------
extern "C" void kernel_launch(void* const* d_in, const int* in_sizes, int n_in,
                              void* d_out, int out_size)
{
    const float* x  = (const float*)d_in[0];
    const float* h0 = (const float*)d_in[1];
    const float* Wz = (const float*)d_in[2];
    const float* bz = (const float*)d_in[3];
    const float* Wh = (const float*)d_in[4];
    const float* bh = (const float*)d_in[5];
    float* out = (float*)d_out;

    convert_kernel<<<512, 256>>>(x);

    cudaFuncSetAttribute(fused_kernel, cudaFuncAttributeMaxDynamicSharedMemorySize, SMEM_FUSED);
    dim3 fgrid(H_ / HSL, B_);            // (4, 32) = 128 CTAs
    fused_kernel<<<fgrid, 512, SMEM_FUSED>>>(Wz, bz, Wh, bh, h0, out);
}

// round 15
// speedup vs baseline: 1.2989x; 1.0571x over previous
#include <cuda_runtime.h>
#include <cuda_fp16.h>
#include <cstdint>

// ---------------- problem dims ----------------
#define B_   32
#define T_   4096
#define DIN_ 256
#define H_   256
#define BT_  (B_ * T_)

// ---------------- fused tiling ------------------
#define TCH   128             // tokens per chunk
#define NCHK  (T_ / TCH)      // 32 chunks
#define HSL   64              // h channels per CTA slice

// smem layout (bytes)
#define SM_A     0                  // 4 K-panels x 16384 (full chunk: 128 tok x 256 halves)
#define SM_W     65536              // 4 K-panels x 16384 (W: 64 z-rows + 64 h-rows)
#define SM_CV    131072             // 128 tok x 64 h x half2 = 32768
#define SM_SEGP  163840             // 8 x 64 floats
#define SM_SEGS  165888             // 8 x 64 floats
#define SM_HC    167936             // 64 floats carry
#define SMEM_FUSED 168192

// cv smem swizzle: word index for (token t, channel h)
#define CVIDX(t, h) ((t) * 64 + ((h) ^ (((t) & 7) << 3)))

// ---------------- scratch ----------------------
__device__ __half g_Xh[(size_t)BT_ * DIN_];

// ---------------- fp32 -> fp16 convert (X only) ----------------
__global__ void __launch_bounds__(256) convert_kernel(const float* __restrict__ X)
{
    const size_t i = (size_t)blockIdx.x * blockDim.x + threadIdx.x;
    const size_t stride = (size_t)gridDim.x * blockDim.x;
    const size_t XF4 = (size_t)BT_ * DIN_ / 4;

    const float4* X4 = reinterpret_cast<const float4*>(X);
    uint2* OX = reinterpret_cast<uint2*>(g_Xh);
    for (size_t j = i; j < XF4; j += stride) {
        float4 v = X4[j];
        __half2 h0 = __floats2half2_rn(v.x, v.y);
        __half2 h1 = __floats2half2_rn(v.z, v.w);
        OX[j] = make_uint2(*reinterpret_cast<uint32_t*>(&h0), *reinterpret_cast<uint32_t*>(&h1));
    }
}

// ---------------- helpers ------------------
__device__ __forceinline__ uint32_t smem_u32(const void* p) {
    uint32_t r;
    asm("{\n\t.reg .u64 t;\n\tcvta.to.shared.u64 t, %1;\n\tcvt.u32.u64 %0, t;\n\t}"
        : "=r"(r) : "l"(p));
    return r;
}
__device__ __forceinline__ void cp16(uint32_t dst, const void* src) {
    asm volatile("cp.async.cg.shared.global [%0], [%1], 16;" :: "r"(dst), "l"(src));
}
#define CP_COMMIT()  asm volatile("cp.async.commit_group;" ::: "memory")
#define CP_WAIT0()   asm volatile("cp.async.wait_group 0;" ::: "memory")
#define SWZ(o) ((o) ^ ((((uint32_t)(o)) >> 3) & 0x70))

__device__ __forceinline__ void ldm_x4(uint32_t& r0, uint32_t& r1, uint32_t& r2, uint32_t& r3,
                                       uint32_t addr) {
    asm volatile("ldmatrix.sync.aligned.m8n8.x4.shared.b16 {%0,%1,%2,%3}, [%4];"
                 : "=r"(r0), "=r"(r1), "=r"(r2), "=r"(r3) : "r"(addr));
}
__device__ __forceinline__ void mma_f16(float* d, const uint32_t* a, uint32_t b0, uint32_t b1) {
    asm volatile("mma.sync.aligned.m16n8k16.row.col.f32.f16.f16.f32 "
                 "{%0,%1,%2,%3}, {%4,%5,%6,%7}, {%8,%9}, {%0,%1,%2,%3};"
                 : "+f"(d[0]), "+f"(d[1]), "+f"(d[2]), "+f"(d[3])
                 : "r"(a[0]), "r"(a[1]), "r"(a[2]), "r"(a[3]), "r"(b0), "r"(b1));
}

__device__ __forceinline__ float tanh_fast(float x) {
    float t;
    asm("tanh.approx.f32 %0, %1;" : "=f"(t) : "f"(x));
    return t;
}
// z = sigmoid(k), c = 1-z, from one tanh
__device__ __forceinline__ void zc_pair(float k, float& z, float& c) {
    float t = tanh_fast(0.5f * k);
    z = fmaf(0.5f, t, 0.5f);
    c = fmaf(-0.5f, t, 0.5f);
}
__device__ __forceinline__ float g_act(float x) {
    if (x >= 0.f) return x + 0.5f;
    float t = tanh_fast(0.5f * x);
    return fmaf(0.5f, t, 0.5f);
}
__device__ __forceinline__ uint32_t pack_h2(float a, float b) {
    __half2 p = __floats2half2_rn(a, b);
    return *reinterpret_cast<uint32_t*>(&p);
}

// ---------------- fused GEMM + activation + scan ----------------
// grid: (slice [0,4), batch [0,32)); block 512 = 16 warps laid out 4(M) x 4(N)
__global__ void __launch_bounds__(512, 1) fused_kernel(
    const float* __restrict__ Wz, const float* __restrict__ bz,
    const float* __restrict__ Wh, const float* __restrict__ bh,
    const float* __restrict__ h0g, float* __restrict__ out)
{
    extern __shared__ char smem[];
    const uint32_t sbase = smem_u32(smem);

    float*   segP = reinterpret_cast<float*>(smem + SM_SEGP);
    float*   segS = reinterpret_cast<float*>(smem + SM_SEGS);
    float*   hcF  = reinterpret_cast<float*>(smem + SM_HC);
    __half2* scvH = reinterpret_cast<__half2*>(smem + SM_CV);
    uint32_t* scvU = reinterpret_cast<uint32_t*>(smem + SM_CV);

    const int tid  = threadIdx.x;
    const int lane = tid & 31;
    const int wid  = tid >> 5;
    const int wm   = wid >> 2;    // 0..3 (token dir, 32 rows each)
    const int wn   = wid & 3;     // 0..3 (h dir, 16 cols each)
    const int grp  = lane >> 2;   // 0..7
    const int tg   = lane & 3;    // 0..3
    const int lrow = ((lane >> 3) & 1) * 8 + (lane & 7);
    const int lkh  = (lane >> 4) * 16;

    const int slice = blockIdx.x;
    const int b     = blockIdx.y;
    const int hbase = slice * HSL;

    // scan-phase mapping
    const int seg = tid >> 6;      // 0..7, 16 tokens each
    const int hch = tid & 63;      // h channel within slice

    // init h carry (g in exact form: one-off, use precise path)
    if (tid < HSL) {
        float x = h0g[b * H_ + hbase + tid];
        float g = (x >= 0.f) ? (x + 0.5f)
                             : __fdividef(1.f, 1.f + __expf(-x));
        hcF[tid] = g;
    }

    // bias preload
    float bzr[2][2], bhr[2][2];
    #pragma unroll
    for (int nt = 0; nt < 2; nt++) {
        int col = hbase + wn * 16 + nt * 8 + 2 * tg;
        bzr[nt][0] = bz[col];     bzr[nt][1] = bz[col + 1];
        bhr[nt][0] = bh[col];     bhr[nt][1] = bh[col + 1];
    }

    const float4* Wz4f = reinterpret_cast<const float4*>(Wz);
    const float4* Wh4f = reinterpret_cast<const float4*>(Wh);
    const uint4*  Xh16 = reinterpret_cast<const uint4*>(g_Xh);

    // ---- prologue: convert this CTA's W slice fp32 -> fp16 swizzled smem ----
    #pragma unroll
    for (int i = 0; i < 8; i++) {
        int q = tid + i * 512;
        int c = q >> 10, rem = q & 1023;
        int r = rem >> 3, u = rem & 7;
        const float4* src = (r < 64) ? (Wz4f + (size_t)(hbase + r) * 64 + c * 16 + u * 2)
                                     : (Wh4f + (size_t)(hbase + r - 64) * 64 + c * 16 + u * 2);
        float4 f0 = src[0], f1 = src[1];
        uint4 o = make_uint4(pack_h2(f0.x, f0.y), pack_h2(f0.z, f0.w),
                             pack_h2(f1.x, f1.y), pack_h2(f1.z, f1.w));
        *reinterpret_cast<uint4*>(smem + SM_W + c * 16384 + SWZ(r * 128 + u * 16)) = o;
    }

    // ---- chunk loader: full 128 tok x 256 halves (64KB) via cp.async ----
    auto ld_chunk = [&](int c) {
        const size_t tok0 = (size_t)b * T_ + (size_t)c * TCH;
        #pragma unroll
        for (int i = 0; i < 8; i++) {
            int q = tid + i * 512;          // 0..4095
            int r = q >> 5;                 // token row 0..127
            int u = q & 31;                 // 16B unit within 512B row
            int p = u >> 3, uu = u & 7;     // K-panel, unit within panel
            cp16(sbase + SM_A + p * 16384 + SWZ(r * 128 + uu * 16),
                 Xh16 + (tok0 + r) * 32 + u);
        }
    };

    float accZ[2][2][4], accH[2][2][4];
    #pragma unroll
    for (int mt = 0; mt < 2; mt++)
        #pragma unroll
        for (int nt = 0; nt < 2; nt++)
            #pragma unroll
            for (int q = 0; q < 4; q++) { accZ[mt][nt][q] = 0.f; accH[mt][nt][q] = 0.f; }

    ld_chunk(0); CP_COMMIT();
    CP_WAIT0();
    __syncthreads();   // W prologue + chunk 0 visible

    #pragma unroll 1
    for (int chunk = 0; chunk < NCHK; chunk++) {
        // ---- GEMM: full chunk, 16 uninterrupted ks iterations ----
        #pragma unroll
        for (int ks = 0; ks < 16; ks++) {
            const uint32_t aB = sbase + SM_A + (ks >> 2) * 16384;
            const uint32_t wB = sbase + SM_W + (ks >> 2) * 16384;
            const int kb = (ks & 3) * 32 + lkh;
            uint32_t a[2][4], z[4], hh[4];
            #pragma unroll
            for (int mt = 0; mt < 2; mt++)
                ldm_x4(a[mt][0], a[mt][1], a[mt][2], a[mt][3],
                       aB + SWZ((wm * 32 + mt * 16 + lrow) * 128 + kb));
            ldm_x4(z[0], z[1], z[2], z[3],
                   wB + SWZ((wn * 16 + lrow) * 128 + kb));
            ldm_x4(hh[0], hh[1], hh[2], hh[3],
                   wB + SWZ((64 + wn * 16 + lrow) * 128 + kb));
            #pragma unroll
            for (int mt = 0; mt < 2; mt++)
                #pragma unroll
                for (int nt = 0; nt < 2; nt++) {
                    mma_f16(accZ[mt][nt], a[mt], z[nt], z[nt + 2]);
                    mma_f16(accH[mt][nt], a[mt], hh[nt], hh[nt + 2]);
                }
        }

        // ---- activation -> cv smem (tanh-based: 1 MUFU per sigmoid) ----
        #pragma unroll
        for (int mt = 0; mt < 2; mt++) {
            #pragma unroll
            for (int nt = 0; nt < 2; nt++) {
                const int col = wn * 16 + nt * 8 + 2 * tg;   // local h
                const int r0  = wm * 32 + mt * 16 + grp;     // local token
                float k0  = accZ[mt][nt][0] + bzr[nt][0];
                float k1  = accZ[mt][nt][1] + bzr[nt][1];
                float k2  = accZ[mt][nt][2] + bzr[nt][0];
                float k3  = accZ[mt][nt][3] + bzr[nt][1];
                float kh0 = accH[mt][nt][0] + bhr[nt][0];
                float kh1 = accH[mt][nt][1] + bhr[nt][1];
                float kh2 = accH[mt][nt][2] + bhr[nt][0];
                float kh3 = accH[mt][nt][3] + bhr[nt][1];
                float z0, c0, z1, c1, z2, c2, z3, c3;
                zc_pair(k0, z0, c0);
                zc_pair(k1, z1, c1);
                zc_pair(k2, z2, c2);
                zc_pair(k3, z3, c3);
                uint2 p0 = make_uint2(pack_h2(c0, z0 * g_act(kh0)),
                                      pack_h2(c1, z1 * g_act(kh1)));
                uint2 p1 = make_uint2(pack_h2(c2, z2 * g_act(kh2)),
                                      pack_h2(c3, z3 * g_act(kh3)));
                *reinterpret_cast<uint2*>(&scvU[CVIDX(r0,     col)]) = p0;
                *reinterpret_cast<uint2*>(&scvU[CVIDX(r0 + 8, col)]) = p1;
            }
        }
        __syncthreads();   // all GEMM A-reads done + cv visible

        // ---- prefetch next chunk; fill overlaps the scan phase ----
        if (chunk + 1 < NCHK) { ld_chunk(chunk + 1); CP_COMMIT(); }

        // ---- segment aggregate (16 tokens per thread) ----
        float P = 1.f, S = 0.f;
        const int tokb = seg * 16;
        #pragma unroll
        for (int j = 0; j < 16; j++) {
            float2 cv = __half22float2(scvH[CVIDX(tokb + j, hch)]);
            S = fmaf(cv.x, S, cv.y);
            P *= cv.x;
        }
        segP[seg * 64 + hch] = P;
        segS[seg * 64 + hch] = S;
        __syncthreads();

        // ---- combine: prefix over segments + carry ----
        float hin = hcF[hch];
        #pragma unroll
        for (int q = 0; q < 7; q++)
            if (q < seg) hin = fmaf(segP[q * 64 + hch], hin, segS[q * 64 + hch]);
        __syncthreads();   // all carry reads done before seg7 overwrites

        // ---- replay + emit ----
        float hv = hin;
        size_t obase = ((size_t)b * T_ + (size_t)chunk * TCH + tokb) * H_ + hbase + hch;
        #pragma unroll
        for (int j = 0; j < 16; j++) {
            float2 cv = __half22float2(scvH[CVIDX(tokb + j, hch)]);
            hv = fmaf(cv.x, hv, cv.y);
            out[obase + (size_t)j * H_] = hv;
        }
        if (seg == 7) hcF[hch] = hv;

        CP_WAIT0();        // next chunk's A resident
        __syncthreads();   // hcF/cv/segP reuse safe + A visible

        // reset accumulators
        #pragma unroll
        for (int mt = 0; mt < 2; mt++)
            #pragma unroll
            for (int nt = 0; nt < 2; nt++)
                #pragma unroll
                for (int q = 0; q < 4; q++) { accZ[mt][nt][q] = 0.f; accH[mt][nt][q] = 0.f; }
    }
}

// ---------------- launch -------------------------------------------------
extern "C" void kernel_launch(void* const* d_in, const int* in_sizes, int n_in,
                              void* d_out, int out_size)
{
    const float* x  = (const float*)d_in[0];
    const float* h0 = (const float*)d_in[1];
    const float* Wz = (const float*)d_in[2];
    const float* bz = (const float*)d_in[3];
    const float* Wh = (const float*)d_in[4];
    const float* bh = (const float*)d_in[5];
    float* out = (float*)d_out;

    convert_kernel<<<512, 256>>>(x);

    cudaFuncSetAttribute(fused_kernel, cudaFuncAttributeMaxDynamicSharedMemorySize, SMEM_FUSED);
    dim3 fgrid(H_ / HSL, B_);            // (4, 32) = 128 CTAs
    fused_kernel<<<fgrid, 512, SMEM_FUSED>>>(Wz, bz, Wh, bh, h0, out);
}